// round 10
// baseline (speedup 1.0000x reference)
#include <cuda_runtime.h>
#include <cuda_bf16.h>
#include <cstdint>
#include <math.h>

#define BATCH 8192
#define TSTEPS 16

// tcgen05 only exists under arch-specific ('a') / family targets.
#if defined(__CUDA_ARCH__) && (defined(__CUDA_ARCH_FEAT_SM103_ALL) || defined(__CUDA_ARCH_FEAT_SM100_ALL) || \
    (defined(__CUDA_ARCH_SPECIFIC__) && (__CUDA_ARCH_SPECIFIC__ >= 1000)) || \
    (defined(__CUDA_ARCH_FAMILY_SPECIFIC__) && (__CUDA_ARCH_FAMILY_SPECIFIC__ >= 1000)))
#define USE_TC 1
#else
#define USE_TC 0
#endif

// ---- smem layout for the TC path (1024-aligned tiles) ----
#define SM_AH0 1024
#define SM_AL0 17408
#define SM_BH0 33792
#define SM_BL0 66560
#define SM_AH1 99328
#define SM_AL1 115712
#define SM_BH1 132096
#define SM_BL1 164864
#define SMEM_SZ 197632
#define SW128(x) ((x) ^ (((x) >> 3) & 0x70))

// Pre-converted weights: SW128-swizzled bf16 hi/lo chunk tiles.
#define WTOT 344064
#define WS3  229376
__device__ __nv_bfloat16 g_wh[WTOT];
__device__ __nv_bfloat16 g_wl[WTOT];
__device__ float g_cue[BATCH * 2];
__device__ float g_w3c0[256], g_w3c1[256];   // W3i cols 0,1 extracted dense

static __device__ __forceinline__ uint32_t smem_u32(const void* p) {
    uint32_t a;
    asm("{ .reg .u64 t; cvta.to.shared.u64 t, %1; cvt.u32.u64 %0, t; }" : "=r"(a) : "l"(p));
    return a;
}
// Single-instruction tanh (MUFU-class).
static __device__ __forceinline__ float ftanh(float x) {
    float r;
    asm("tanh.approx.f32 %0, %1;" : "=f"(r) : "f"(x));
    return r;
}
#if USE_TC
static __device__ __forceinline__ uint32_t elect_one() {
    uint32_t p;
    asm volatile("{ .reg .pred p; elect.sync _|p, 0xFFFFFFFF; selp.b32 %0, 1, 0, p; }" : "=r"(p));
    return p;
}
#endif
#define MBARRIER_INIT(a, c) \
    asm volatile("mbarrier.init.shared.b64 [%0], %1;" :: "r"((uint32_t)(a)), "r"((uint32_t)(c)) : "memory")
// Non-blocking test_wait poll, bounded (~80ms) so a lost arrive fails fast.
#define MBAR_WAIT(mb, par) do { \
    uint32_t _m = (uint32_t)(mb), _p = (uint32_t)(par), _d = 0; \
    for (int _i = 0; _i < (1 << 20) && !_d; _i++) { \
        asm volatile("{ .reg .pred p; mbarrier.test_wait.parity.acquire.cta.shared::cta.b64 p, [%1], %2; selp.b32 %0,1,0,p; }" \
            : "=r"(_d) : "r"(_m), "r"(_p) : "memory"); \
    } \
} while (0)
#define TC_ALLOC(a, n) asm volatile("tcgen05.alloc.cta_group::1.sync.aligned.shared::cta.b32 [%0], %1;" :: "r"((uint32_t)(a)), "r"((uint32_t)(n)) : "memory")
#define TC_DEALLOC(t, n) asm volatile("tcgen05.dealloc.cta_group::1.sync.aligned.b32 %0, %1;" :: "r"(t), "r"((uint32_t)(n)))
#define TC_RELINQ() asm volatile("tcgen05.relinquish_alloc_permit.cta_group::1.sync.aligned;")
#define TC_COMMIT(mb) asm volatile("tcgen05.commit.cta_group::1.mbarrier::arrive::one.shared::cluster.b64 [%0];" :: "r"((uint32_t)(mb)) : "memory")
#define TC_FENCE_BEFORE() asm volatile("tcgen05.fence::before_thread_sync;" ::: "memory")
#define TC_FENCE_AFTER()  asm volatile("tcgen05.fence::after_thread_sync;"  ::: "memory")
#define TC_WAIT_LD() asm volatile("tcgen05.wait::ld.sync.aligned;" ::: "memory")
#define TC_WAIT_ST() asm volatile("tcgen05.wait::st.sync.aligned;" ::: "memory")
#define FENCE_ASYNC() asm volatile("fence.proxy.async.shared::cta;" ::: "memory")

#define TC_LD_X32(r, a) \
    asm volatile("tcgen05.ld.sync.aligned.32x32b.x32.b32 " \
        "{%0,%1,%2,%3,%4,%5,%6,%7,%8,%9,%10,%11,%12,%13,%14,%15," \
        "%16,%17,%18,%19,%20,%21,%22,%23,%24,%25,%26,%27,%28,%29,%30,%31}, [%32];" \
        : "=r"((r)[0]),"=r"((r)[1]),"=r"((r)[2]),"=r"((r)[3]),"=r"((r)[4]),"=r"((r)[5]),"=r"((r)[6]),"=r"((r)[7]), \
          "=r"((r)[8]),"=r"((r)[9]),"=r"((r)[10]),"=r"((r)[11]),"=r"((r)[12]),"=r"((r)[13]),"=r"((r)[14]),"=r"((r)[15]), \
          "=r"((r)[16]),"=r"((r)[17]),"=r"((r)[18]),"=r"((r)[19]),"=r"((r)[20]),"=r"((r)[21]),"=r"((r)[22]),"=r"((r)[23]), \
          "=r"((r)[24]),"=r"((r)[25]),"=r"((r)[26]),"=r"((r)[27]),"=r"((r)[28]),"=r"((r)[29]),"=r"((r)[30]),"=r"((r)[31]) \
        : "r"(a))

#define DESC_BASE ((2ull << 61) | (1ull << 46) | (64ull << 32) | (1ull << 16))
#define MKDESC(a) (DESC_BASE | (uint64_t)((((uint32_t)(a)) >> 4) & 0x3FFF))
// bf16 idesc: dtype=F32(1)<<4, atype=btype=BF16(1), N/8<<17, M/16<<24 (M=128)
#define ID_N256 ((1u << 4) | (1u << 7) | (1u << 10) | (32u << 17) | (8u << 24))
#define ID_N64  ((1u << 4) | (1u << 7) | (1u << 10) | (8u << 17)  | (8u << 24))

#if USE_TC
static __device__ __forceinline__ void mma_f16(uint32_t d, uint64_t a, uint64_t b,
                                               uint32_t idesc, uint32_t en) {
    asm volatile("{ .reg .pred p; setp.ne.u32 p, %5, 0; "
                 "tcgen05.mma.cta_group::1.kind::f16 [%0], %1, %2, %3, {%4,%4,%4,%4}, p; }"
                 :: "r"(d), "l"(a), "l"(b), "r"(idesc), "r"(0u), "r"(en) : "memory");
}
#endif

static __device__ __forceinline__ unsigned pk(float a, float b) {
    __nv_bfloat162 h = __floats2bfloat162_rn(a, b);
    return *reinterpret_cast<unsigned*>(&h);
}
static __device__ __forceinline__ float bfl(float x) {
    return __bfloat162float(__float2bfloat16_rn(x));
}

// Prep: convert W[n][col0 + chunk*64 + k] (row stride ld) into swizzled hi/lo
// chunk tiles at g_wh/g_wl + dstoff. One thread per element.
__global__ void prep_w(const float* __restrict__ W, int ld, int col0, int N, int nch,
                       int dstoff) {
    int idx = blockIdx.x * 256 + threadIdx.x;
    if (idx >= N * nch * 64) return;
    int chunk = idx / (N * 64), rem = idx - chunk * N * 64;
    int n = rem >> 6, k = rem & 63;
    float v = W[(size_t)n * ld + col0 + chunk * 64 + k];
    float h = bfl(v);
    int off = dstoff + chunk * N * 64 + (SW128(n * 128 + k * 2) >> 1);
    g_wh[off] = __float2bfloat16_rn(v);
    g_wl[off] = __float2bfloat16_rn(v - h);
}
__global__ void prep_cue_w(const float* __restrict__ W3i) {
    int i = threadIdx.x;                      // 256 threads
    g_w3c0[i] = W3i[(size_t)i * 130];
    g_w3c1[i] = W3i[(size_t)i * 130 + 1];
}

// ---- A (activation) hi/lo bf16 staging into SW128 tiles (rows of 64 elts = 128B) ----
static __device__ __forceinline__ void stgA(char* hiD, char* loD, const float* __restrict__ S,
                                            int ld, int c0, int tid) {
#pragma unroll
    for (int q = 0; q < 8; q++) {            // 128 rows x 16 float4
        int lin = tid + q * 256, row = lin >> 4, g = lin & 15;
        float4 v = *reinterpret_cast<const float4*>(S + (size_t)row * ld + c0 + g * 4);
        float hx = bfl(v.x), hy = bfl(v.y), hz = bfl(v.z), hw = bfl(v.w);
        uint2 H, L;
        H.x = pk(v.x, v.y); H.y = pk(v.z, v.w);
        L.x = pk(v.x - hx, v.y - hy); L.y = pk(v.z - hz, v.w - hw);
        int off = SW128(row * 128 + g * 8);
        *reinterpret_cast<uint2*>(hiD + off) = H;
        *reinterpret_cast<uint2*>(loD + off) = L;
    }
}

#if USE_TC
// Two mbarriers (one per staging buffer) with per-buffer use counters.
struct Ctx {
    uint32_t sb, tb;
    int tid, ph;
    int use_[2];
    __device__ __forceinline__ uint32_t mb(int b) const { return sb + 8 + 8 * b; }
    __device__ __forceinline__ void wait_buf(int b) {
        if (use_[b] > 0) MBAR_WAIT(mb(b), (uint32_t)((use_[b] - 1) & 1));
    }
    __device__ __forceinline__ void wait_all() {
        int lb = (ph - 1) & 1;
        MBAR_WAIT(mb(lb), (uint32_t)((use_[lb] - 1) & 1));
    }
};
// D(+)= A[128xK] @ W^T; W pre-converted at g_wh/g_wl + woff (chunk tiles of NB*64 elts).
template <int NB>
static __device__ __forceinline__ void gemm_seg(Ctx& c, char* sm,
                                                const float* A, int ldA, int woff,
                                                int nch, uint32_t dtm, uint32_t idesc,
                                                bool fresh) {
    for (int kc = 0; kc < nch; kc++) {
        int b = c.ph & 1;
        c.wait_buf(b);                       // previous MMA on this buffer done
        char* AH = sm + (b ? SM_AH1 : SM_AH0);
        char* AL = sm + (b ? SM_AL1 : SM_AL0);
        stgA(AH, AL, A, ldA, kc * 64, c.tid);
        {   // B: straight uint4 copy of pre-swizzled tiles
            const uint4* sh = reinterpret_cast<const uint4*>(g_wh + woff + (size_t)kc * NB * 64);
            const uint4* sl = reinterpret_cast<const uint4*>(g_wl + woff + (size_t)kc * NB * 64);
            uint4* dh = reinterpret_cast<uint4*>(sm + (b ? SM_BH1 : SM_BH0));
            uint4* dl = reinterpret_cast<uint4*>(sm + (b ? SM_BL1 : SM_BL0));
#pragma unroll
            for (int q = 0; q < NB / 32; q++) {
                int i = c.tid + q * 256;
                dh[i] = sh[i];
                dl[i] = sl[i];
            }
        }
        FENCE_ASYNC();
        __syncthreads();
        if ((c.tid >> 5) == 0 && elect_one()) {
            TC_FENCE_AFTER();
            uint64_t ah = MKDESC(c.sb + (b ? SM_AH1 : SM_AH0));
            uint64_t al = MKDESC(c.sb + (b ? SM_AL1 : SM_AL0));
            uint64_t bh = MKDESC(c.sb + (b ? SM_BH1 : SM_BH0));
            uint64_t bl = MKDESC(c.sb + (b ? SM_BL1 : SM_BL0));
#pragma unroll
            for (int s = 0; s < 4; s++)
                mma_f16(dtm, ah + 2 * s, bh + 2 * s, idesc, (fresh && kc == 0 && s == 0) ? 0u : 1u);
#pragma unroll
            for (int s = 0; s < 4; s++) mma_f16(dtm, ah + 2 * s, bl + 2 * s, idesc, 1u);
#pragma unroll
            for (int s = 0; s < 4; s++) mma_f16(dtm, al + 2 * s, bh + 2 * s, idesc, 1u);
            TC_COMMIT(c.mb(b));
        }
        c.use_[b]++;
        c.ph++;
    }
}
#endif  // USE_TC

// ---- FFMA fallback GEMM helpers (native [N][K] weights) ----
static __device__ void fg256(float acc[8][8], const float* __restrict__ A, int ldA, int K,
                             const float* __restrict__ W, int ldW, int col0, int mode,
                             float* Ws, float* As, int tid, int tr, int tc) {
    for (int k0 = 0; k0 < K; k0 += 32) {
        __syncthreads();
        if (mode == 0) {
#pragma unroll
            for (int q = 0; q < 8; q++) {
                int lin = tid + q * 256, n = lin >> 3, p4 = lin & 7;
                float4 v = *reinterpret_cast<const float4*>(W + (size_t)n * ldW + col0 + k0 + p4 * 4);
                Ws[(p4 * 4 + 0) * 260 + n] = v.x; Ws[(p4 * 4 + 1) * 260 + n] = v.y;
                Ws[(p4 * 4 + 2) * 260 + n] = v.z; Ws[(p4 * 4 + 3) * 260 + n] = v.w;
            }
        } else {
#pragma unroll
            for (int q = 0; q < 16; q++) {
                int lin = tid + q * 256, n = lin >> 4, g = lin & 15;
                float2 v = *reinterpret_cast<const float2*>(W + (size_t)n * ldW + col0 + k0 + g * 2);
                Ws[(g * 2 + 0) * 260 + n] = v.x;
                Ws[(g * 2 + 1) * 260 + n] = v.y;
            }
        }
#pragma unroll
        for (int q = 0; q < 2; q++) {
            int lin = tid + q * 256, row = lin >> 3, p4 = lin & 7;
            float4 v = *reinterpret_cast<const float4*>(A + (size_t)row * ldA + k0 + p4 * 4);
            As[(p4 * 4 + 0) * 65 + row] = v.x; As[(p4 * 4 + 1) * 65 + row] = v.y;
            As[(p4 * 4 + 2) * 65 + row] = v.z; As[(p4 * 4 + 3) * 65 + row] = v.w;
        }
        __syncthreads();
#pragma unroll 4
        for (int kk = 0; kk < 32; kk++) {
            float a[8], w[8];
#pragma unroll
            for (int i = 0; i < 8; i++) a[i] = As[kk * 65 + tr + 8 * i];
#pragma unroll
            for (int j = 0; j < 8; j++) w[j] = Ws[kk * 260 + tc + 32 * j];
#pragma unroll
            for (int i = 0; i < 8; i++)
#pragma unroll
                for (int j = 0; j < 8; j++) acc[i][j] = fmaf(a[i], w[j], acc[i][j]);
        }
    }
}
static __device__ void fg64(float acc[8][2], const float* __restrict__ A, int ldA, int K,
                            const float* __restrict__ W, float* Ws, float* As,
                            int tid, int tr, int tc) {
    for (int k0 = 0; k0 < K; k0 += 32) {
        __syncthreads();
#pragma unroll
        for (int q = 0; q < 2; q++) {
            int lin = tid + q * 256, n = lin >> 3, p4 = lin & 7;
            float4 v = *reinterpret_cast<const float4*>(W + (size_t)n * 256 + k0 + p4 * 4);
            Ws[(p4 * 4 + 0) * 65 + n] = v.x; Ws[(p4 * 4 + 1) * 65 + n] = v.y;
            Ws[(p4 * 4 + 2) * 65 + n] = v.z; Ws[(p4 * 4 + 3) * 65 + n] = v.w;
        }
#pragma unroll
        for (int q = 0; q < 2; q++) {
            int lin = tid + q * 256, row = lin >> 3, p4 = lin & 7;
            float4 v = *reinterpret_cast<const float4*>(A + (size_t)row * ldA + k0 + p4 * 4);
            As[(p4 * 4 + 0) * 65 + row] = v.x; As[(p4 * 4 + 1) * 65 + row] = v.y;
            As[(p4 * 4 + 2) * 65 + row] = v.z; As[(p4 * 4 + 3) * 65 + row] = v.w;
        }
        __syncthreads();
#pragma unroll 8
        for (int kk = 0; kk < 32; kk++) {
            float a[8];
#pragma unroll
            for (int i = 0; i < 8; i++) a[i] = As[kk * 65 + tr + 8 * i];
            float w0 = Ws[kk * 65 + tc], w1 = Ws[kk * 65 + tc + 32];
#pragma unroll
            for (int i = 0; i < 8; i++) {
                acc[i][0] = fmaf(a[i], w0, acc[i][0]);
                acc[i][1] = fmaf(a[i], w1, acc[i][1]);
            }
        }
    }
}

struct Params {
    const float* x;
    const float *W1i, *b1i, *W1h, *b1h, *Wf1, *bf1, *W1o, *b1o;
    const float *W2i, *b2i, *W2h, *b2h, *Wf2, *bf2, *W2o, *b2o;
    const float *W3i, *b3i, *W3h, *b3h, *W3o, *b3o, *Wfc, *bfc;
    float *h1, *h2, *h3, *h4;
    float *oseq, *o1, *o2, *f1, *f2, *ofa;
};

__global__ void init_kernel(const float* __restrict__ cue,
                            const float* __restrict__ hc1, const float* __restrict__ hc2,
                            const float* __restrict__ hc3, const float* __restrict__ hc4,
                            float* __restrict__ h1, float* __restrict__ h2,
                            float* __restrict__ h3, float* __restrict__ h4,
                            float* __restrict__ cue_arr) {
    int idx = blockIdx.x * blockDim.x + threadIdx.x;
    if (idx < BATCH * 256) { h1[idx] = hc1[idx]; h2[idx] = hc2[idx]; h3[idx] = hc3[idx]; }
    if (idx < BATCH * 64) h4[idx] = hc4[idx];
    if (idx < BATCH) {
        float c = cue[idx], c0 = c * 10.0f, c1 = 10.0f * fabsf(c - 1.0f);
        g_cue[idx * 2] = c0; g_cue[idx * 2 + 1] = c1;
#pragma unroll
        for (int t = 0; t < TSTEPS; t++) {
            cue_arr[(size_t)t * BATCH * 2 + idx * 2] = c0;
            cue_arr[(size_t)t * BATCH * 2 + idx * 2 + 1] = c1;
        }
    }
}

__global__ __launch_bounds__(256, 1) __cluster_dims__(1, 1, 1) void stack12_k(Params p, int t) {
    extern __shared__ char sm[];
    const int tid = threadIdx.x, wid = tid >> 5, lane = tid & 31;
    const int s = blockIdx.y, row0 = blockIdx.x * 128;

    const float* bi = s ? p.b2i : p.b1i;
    const float* bh = s ? p.b2h : p.b1h;
    const float* bf = s ? p.bf2 : p.bf1;
    const float* bo = s ? p.b2o : p.b1o;
    float* hst  = (s ? p.h2 : p.h1) + (size_t)row0 * 256;
    float* fout = (s ? p.f2 : p.f1) + ((size_t)t * BATCH + row0) * 256;
    float* oout = (s ? p.o2 : p.o1) + ((size_t)t * BATCH + row0) * 64;
    const float* xt = p.x + ((size_t)t * BATCH + row0) * 64;
    const float* h4 = p.h4 + (size_t)row0 * 64;

#if USE_TC
    const int woff = s ? 114688 : 0;
    const uint32_t sb = smem_u32(sm);
    if (wid == 0) { TC_ALLOC(sb, 512); TC_RELINQ(); }
    if (tid == 0) { MBARRIER_INIT(sb + 8, 1); MBARRIER_INIT(sb + 16, 1); }
    __syncthreads();
    uint32_t tb;
    asm volatile("ld.shared.b32 %0, [%1];" : "=r"(tb) : "r"(sb));
    Ctx c{sb, tb, tid, 0, {0, 0}};

    const int sub = wid & 3, r = sub * 32 + lane, hb = (wid >> 2) * 128;

    // ONE fused MMA chain, no intermediate epilogue:
    //   D2 (cols 256..511) = h4 @ Wf^T        (feed)
    //   D1 (cols 0..255)   = x @ Wi^T + h @ Wh^T
    gemm_seg<256>(c, sm, h4, 64, woff + 0, 1, tb + 256, ID_N256, true);
    gemm_seg<256>(c, sm, xt, 64, woff + 16384, 1, tb, ID_N256, true);
    gemm_seg<256>(c, sm, hst, 256, woff + 32768, 4, tb, ID_N256, false);
    c.wait_all();
    TC_FENCE_AFTER();
    // Single epilogue: f = D2+bf -> fout; h = tanh(D1 + tanh(f) + bi + bh) -> hst
#pragma unroll
    for (int cc = 0; cc < 4; cc++) {
        int gc = hb + cc * 32;
        uint32_t rg2[32];
        TC_LD_X32(rg2, tb + 256 + gc);           // feed
        TC_WAIT_LD();
        float seed[32];
#pragma unroll
        for (int j = 0; j < 32; j++) {
            float fv = __uint_as_float(rg2[j]) + bf[gc + j];
            rg2[j] = __float_as_uint(fv);
            seed[j] = ftanh(fv) + bi[gc + j] + bh[gc + j];
        }
#pragma unroll
        for (int j4 = 0; j4 < 8; j4++)
            *reinterpret_cast<float4*>(fout + (size_t)r * 256 + gc + j4 * 4) =
                make_float4(__uint_as_float(rg2[j4 * 4]), __uint_as_float(rg2[j4 * 4 + 1]),
                            __uint_as_float(rg2[j4 * 4 + 2]), __uint_as_float(rg2[j4 * 4 + 3]));
        uint32_t rg1[32];
        TC_LD_X32(rg1, tb + gc);                 // main
        TC_WAIT_LD();
#pragma unroll
        for (int j4 = 0; j4 < 8; j4++)
            *reinterpret_cast<float4*>(hst + (size_t)r * 256 + gc + j4 * 4) =
                make_float4(ftanh(__uint_as_float(rg1[j4 * 4]) + seed[j4 * 4]),
                            ftanh(__uint_as_float(rg1[j4 * 4 + 1]) + seed[j4 * 4 + 1]),
                            ftanh(__uint_as_float(rg1[j4 * 4 + 2]) + seed[j4 * 4 + 2]),
                            ftanh(__uint_as_float(rg1[j4 * 4 + 3]) + seed[j4 * 4 + 3]));
    }
    TC_FENCE_BEFORE();
    __syncthreads();   // all h visible before head staging reads hst

    // Head: o = tanh(h @ Wo^T + bo).  Reuses D2 cols (fully read above).
    gemm_seg<64>(c, sm, hst, 256, woff + 98304, 4, tb + 256, ID_N64, true);
    c.wait_all();
    TC_FENCE_AFTER();
    {
        int cb = (wid >> 2) * 32;
        uint32_t rg[32];
        TC_LD_X32(rg, tb + 256 + cb);
        TC_WAIT_LD();
#pragma unroll
        for (int j4 = 0; j4 < 8; j4++)
            *reinterpret_cast<float4*>(oout + (size_t)r * 64 + cb + j4 * 4) =
                make_float4(ftanh(__uint_as_float(rg[j4 * 4]) + bo[cb + j4 * 4]),
                            ftanh(__uint_as_float(rg[j4 * 4 + 1]) + bo[cb + j4 * 4 + 1]),
                            ftanh(__uint_as_float(rg[j4 * 4 + 2]) + bo[cb + j4 * 4 + 2]),
                            ftanh(__uint_as_float(rg[j4 * 4 + 3]) + bo[cb + j4 * 4 + 3]));
    }
    TC_FENCE_BEFORE();
    __syncthreads();
    if (wid == 0) TC_DEALLOC(tb, 512);
#else
    // ---------------- FFMA fallback ----------------
    const float* Wi = s ? p.W2i : p.W1i;
    const float* Wh = s ? p.W2h : p.W1h;
    const float* Wf = s ? p.Wf2 : p.Wf1;
    const float* Wo = s ? p.W2o : p.W1o;
    float* Ws = reinterpret_cast<float*>(sm);
    float* As = Ws + 32 * 260;
    const int tr = wid, tc = lane;
    for (int hf = 0; hf < 2; hf++) {
        const float* Ah4 = h4 + hf * 64 * 64;
        const float* Axt = xt + hf * 64 * 64;
        float* hh = hst + hf * 64 * 256;
        float* ff = fout + hf * 64 * 256;
        float* oo = oout + hf * 64 * 64;

        float acc[8][8];
#pragma unroll
        for (int i = 0; i < 8; i++)
#pragma unroll
            for (int j = 0; j < 8; j++) acc[i][j] = 0.0f;
        fg256(acc, Ah4, 64, 64, Wf, 64, 0, 0, Ws, As, tid, tr, tc);
#pragma unroll
        for (int i = 0; i < 8; i++) {
            int rr = tr + 8 * i;
#pragma unroll
            for (int j = 0; j < 8; j++) {
                int cc = tc + 32 * j;
                float fv = acc[i][j] + bf[cc];
                ff[rr * 256 + cc] = fv;
                acc[i][j] = tanhf(fv) + bi[cc] + bh[cc];
            }
        }
        fg256(acc, Axt, 64, 64, Wi, 64, 0, 0, Ws, As, tid, tr, tc);
        fg256(acc, hh, 256, 256, Wh, 256, 0, 0, Ws, As, tid, tr, tc);
#pragma unroll
        for (int i = 0; i < 8; i++) {
            int rr = tr + 8 * i;
#pragma unroll
            for (int j = 0; j < 8; j++) hh[rr * 256 + tc + 32 * j] = tanhf(acc[i][j]);
        }
        float oacc[8][2];
#pragma unroll
        for (int i = 0; i < 8; i++) { oacc[i][0] = 0.0f; oacc[i][1] = 0.0f; }
        fg64(oacc, hh, 256, 256, Wo, Ws, As, tid, tr, tc);
#pragma unroll
        for (int i = 0; i < 8; i++) {
            int rr = tr + 8 * i;
            oo[rr * 64 + tc]      = tanhf(oacc[i][0] + bo[tc]);
            oo[rr * 64 + tc + 32] = tanhf(oacc[i][1] + bo[tc + 32]);
        }
        __syncthreads();
    }
#endif
}

__global__ __launch_bounds__(256, 1) __cluster_dims__(1, 1, 1) void stack3_k(Params p, int t) {
    extern __shared__ char sm[];
    const int tid = threadIdx.x, wid = tid >> 5, lane = tid & 31;
    const int row0 = blockIdx.x * 128;

    const float* o1t = p.o1 + ((size_t)t * BATCH + row0) * 64;
    const float* o2t = p.o2 + ((size_t)t * BATCH + row0) * 64;
    float* h3 = p.h3 + (size_t)row0 * 256;
    float* h4 = p.h4 + (size_t)row0 * 64;

#if USE_TC
    const uint32_t sb = smem_u32(sm);
    if (wid == 0) { TC_ALLOC(sb, 512); TC_RELINQ(); }
    if (tid == 0) { MBARRIER_INIT(sb + 8, 1); MBARRIER_INIT(sb + 16, 1); }
    __syncthreads();
    uint32_t tb;
    asm volatile("ld.shared.b32 %0, [%1];" : "=r"(tb) : "r"(sb));
    Ctx c{sb, tb, tid, 0, {0, 0}};

    const int sub = wid & 3, r = sub * 32 + lane, hb = (wid >> 2) * 128;

    // Fused MMA chain (cue term added in epilogue, no seed round-trip):
    gemm_seg<256>(c, sm, o1t, 64, WS3 + 0, 1, tb, ID_N256, true);
    gemm_seg<256>(c, sm, o2t, 64, WS3 + 16384, 1, tb, ID_N256, false);
    gemm_seg<256>(c, sm, h3, 256, WS3 + 32768, 4, tb, ID_N256, false);
    c.wait_all();
    TC_FENCE_AFTER();
    {
        float c0 = g_cue[(row0 + r) * 2], c1 = g_cue[(row0 + r) * 2 + 1];
#pragma unroll
        for (int cc = 0; cc < 4; cc++) {
            int gc = hb + cc * 32;
            uint32_t rg[32];
            TC_LD_X32(rg, tb + gc);
            TC_WAIT_LD();
            float hv[32];
#pragma unroll
            for (int j = 0; j < 32; j++) {
                int col = gc + j;
                hv[j] = ftanh(__uint_as_float(rg[j]) + c0 * g_w3c0[col] + c1 * g_w3c1[col] +
                              p.b3i[col] + p.b3h[col]);
            }
#pragma unroll
            for (int j4 = 0; j4 < 8; j4++)
                *reinterpret_cast<float4*>(h3 + (size_t)r * 256 + gc + j4 * 4) =
                    make_float4(hv[j4 * 4], hv[j4 * 4 + 1], hv[j4 * 4 + 2], hv[j4 * 4 + 3]);
        }
    }
    TC_FENCE_BEFORE();
    __syncthreads();

    gemm_seg<64>(c, sm, h3, 256, WS3 + 98304, 4, tb + 256, ID_N64, true);
    c.wait_all();
    TC_FENCE_AFTER();
    float* ofs = reinterpret_cast<float*>(sm + 1024);   // [128][65] — buffers dead now
    {
        int cb = (wid >> 2) * 32;
        uint32_t rg[32];
        TC_LD_X32(rg, tb + 256 + cb);
        TC_WAIT_LD();
        float ov[32];
#pragma unroll
        for (int j = 0; j < 32; j++) {
            float o = __uint_as_float(rg[j]) + p.b3o[cb + j];
            ov[j] = o;
            ofs[r * 65 + cb + j] = fmaxf(o, 0.0f);
        }
#pragma unroll
        for (int j4 = 0; j4 < 8; j4++) {
            *reinterpret_cast<float4*>(h4 + (size_t)r * 64 + cb + j4 * 4) =
                make_float4(ov[j4 * 4], ov[j4 * 4 + 1], ov[j4 * 4 + 2], ov[j4 * 4 + 3]);
            *reinterpret_cast<float4*>(p.ofa + ((size_t)t * BATCH + row0 + r) * 64 + cb + j4 * 4) =
                make_float4(fmaxf(ov[j4 * 4], 0.0f), fmaxf(ov[j4 * 4 + 1], 0.0f),
                            fmaxf(ov[j4 * 4 + 2], 0.0f), fmaxf(ov[j4 * 4 + 3], 0.0f));
        }
    }
    TC_FENCE_BEFORE();
    __syncthreads();
    {
        int rr = tid >> 1, cc2 = tid & 1;
        float sum = p.bfc[cc2];
#pragma unroll
        for (int k = 0; k < 64; k++) sum = fmaf(ofs[rr * 65 + k], p.Wfc[cc2 * 64 + k], sum);
        p.oseq[((size_t)t * BATCH + row0 + rr) * 2 + cc2] = sum;
    }
    __syncthreads();
    if (wid == 0) TC_DEALLOC(tb, 512);
#else
    // ---------------- FFMA fallback ----------------
    float* Ws = reinterpret_cast<float*>(sm);
    float* As = Ws + 32 * 260;
    float* ofs = reinterpret_cast<float*>(sm + 48 * 1024);
    const int tr = wid, tc = lane;
    for (int hf = 0; hf < 2; hf++) {
        const int r0g = row0 + hf * 64;
        const float* Ao1 = o1t + hf * 64 * 64;
        const float* Ao2 = o2t + hf * 64 * 64;
        float* hh = h3 + hf * 64 * 256;
        float* h4h = h4 + hf * 64 * 64;

        float acc[8][8];
#pragma unroll
        for (int i = 0; i < 8; i++) {
            int rg = r0g + tr + 8 * i;
            float c0 = g_cue[rg * 2], c1 = g_cue[rg * 2 + 1];
#pragma unroll
            for (int j = 0; j < 8; j++) {
                int col = tc + 32 * j;
                acc[i][j] = c0 * p.W3i[(size_t)col * 130] + c1 * p.W3i[(size_t)col * 130 + 1];
            }
        }
        fg256(acc, Ao1, 64, 64, p.W3i, 130, 2, 1, Ws, As, tid, tr, tc);
        fg256(acc, Ao2, 64, 64, p.W3i, 130, 66, 1, Ws, As, tid, tr, tc);
        fg256(acc, hh, 256, 256, p.W3h, 256, 0, 0, Ws, As, tid, tr, tc);
#pragma unroll
        for (int i = 0; i < 8; i++) {
            int rr = tr + 8 * i;
#pragma unroll
            for (int j = 0; j < 8; j++) {
                int col = tc + 32 * j;
                hh[rr * 256 + col] = tanhf(acc[i][j] + p.b3i[col] + p.b3h[col]);
            }
        }
        float oacc[8][2];
#pragma unroll
        for (int i = 0; i < 8; i++) { oacc[i][0] = 0.0f; oacc[i][1] = 0.0f; }
        fg64(oacc, hh, 256, 256, p.W3o, Ws, As, tid, tr, tc);
#pragma unroll
        for (int i = 0; i < 8; i++) {
            int rr = tr + 8 * i;
#pragma unroll
            for (int j = 0; j < 2; j++) {
                int col = tc + 32 * j;
                float o = oacc[i][j] + p.b3o[col];
                float of = fmaxf(o, 0.0f);
                h4h[rr * 64 + col] = o;
                p.ofa[((size_t)t * BATCH + r0g + rr) * 64 + col] = of;
                ofs[rr * 66 + col] = of;
            }
        }
        __syncthreads();
        if (tid < 128) {
            int rr = tid >> 1, cc2 = tid & 1;
            float sum = p.bfc[cc2];
#pragma unroll
            for (int k = 0; k < 64; k++) sum = fmaf(ofs[rr * 66 + k], p.Wfc[cc2 * 64 + k], sum);
            p.oseq[((size_t)t * BATCH + r0g + rr) * 2 + cc2] = sum;
        }
        __syncthreads();
    }
#endif
}

extern "C" void kernel_launch(void* const* d_in, const int* in_sizes, int n_in,
                              void* d_out, int out_size) {
    float* out = (float*)d_out;
    size_t off = 0;
    float* oseq = out + off; off += (size_t)TSTEPS * BATCH * 2;
    float* h1 = out + off; off += (size_t)BATCH * 256;
    float* h2 = out + off; off += (size_t)BATCH * 256;
    float* h3 = out + off; off += (size_t)BATCH * 256;
    float* h4 = out + off; off += (size_t)BATCH * 64;
    float* o1 = out + off; off += (size_t)TSTEPS * BATCH * 64;
    float* o2 = out + off; off += (size_t)TSTEPS * BATCH * 64;
    float* cue_arr = out + off; off += (size_t)TSTEPS * BATCH * 2;
    float* f1 = out + off; off += (size_t)TSTEPS * BATCH * 256;
    float* f2 = out + off; off += (size_t)TSTEPS * BATCH * 256;
    float* ofa = out + off;

    Params p;
    p.x = (const float*)d_in[0];
    p.W1i = (const float*)d_in[6];  p.b1i = (const float*)d_in[7];
    p.W1h = (const float*)d_in[8];  p.b1h = (const float*)d_in[9];
    p.Wf1 = (const float*)d_in[10]; p.bf1 = (const float*)d_in[11];
    p.W1o = (const float*)d_in[12]; p.b1o = (const float*)d_in[13];
    p.W2i = (const float*)d_in[14]; p.b2i = (const float*)d_in[15];
    p.W2h = (const float*)d_in[16]; p.b2h = (const float*)d_in[17];
    p.Wf2 = (const float*)d_in[18]; p.bf2 = (const float*)d_in[19];
    p.W2o = (const float*)d_in[20]; p.b2o = (const float*)d_in[21];
    p.W3i = (const float*)d_in[22]; p.b3i = (const float*)d_in[23];
    p.W3h = (const float*)d_in[24]; p.b3h = (const float*)d_in[25];
    p.W3o = (const float*)d_in[26]; p.b3o = (const float*)d_in[27];
    p.Wfc = (const float*)d_in[28]; p.bfc = (const float*)d_in[29];
    p.h1 = h1; p.h2 = h2; p.h3 = h3; p.h4 = h4;
    p.oseq = oseq; p.o1 = o1; p.o2 = o2; p.f1 = f1; p.f2 = f2; p.ofa = ofa;

    cudaFuncSetAttribute(stack12_k, cudaFuncAttributeMaxDynamicSharedMemorySize, SMEM_SZ);
    cudaFuncSetAttribute(stack3_k, cudaFuncAttributeMaxDynamicSharedMemorySize, SMEM_SZ);

    // Pre-convert weights into swizzled bf16 hi/lo chunk tiles.
    struct { const float* W; int ld, col0, N, nch, dst; } pw[12] = {
        {p.Wf1, 64, 0, 256, 1, 0},        {p.W1i, 64, 0, 256, 1, 16384},
        {p.W1h, 256, 0, 256, 4, 32768},   {p.W1o, 256, 0, 64, 4, 98304},
        {p.Wf2, 64, 0, 256, 1, 114688},   {p.W2i, 64, 0, 256, 1, 131072},
        {p.W2h, 256, 0, 256, 4, 147456},  {p.W2o, 256, 0, 64, 4, 212992},
        {p.W3i, 130, 2, 256, 1, WS3},     {p.W3i, 130, 66, 256, 1, WS3 + 16384},
        {p.W3h, 256, 0, 256, 4, WS3 + 32768}, {p.W3o, 256, 0, 64, 4, WS3 + 98304},
    };
    for (int i = 0; i < 12; i++) {
        int n = pw[i].N * pw[i].nch * 64;
        prep_w<<<(n + 255) / 256, 256>>>(pw[i].W, pw[i].ld, pw[i].col0,
                                         pw[i].N, pw[i].nch, pw[i].dst);
    }
    prep_cue_w<<<1, 256>>>(p.W3i);

    init_kernel<<<(BATCH * 256) / 256, 256>>>((const float*)d_in[1], (const float*)d_in[2],
                                              (const float*)d_in[3], (const float*)d_in[4],
                                              (const float*)d_in[5], h1, h2, h3, h4, cue_arr);
    for (int t = 0; t < TSTEPS; t++) {
        stack12_k<<<dim3(BATCH / 128, 2), 256, SMEM_SZ>>>(p, t);
        stack3_k<<<BATCH / 128, 256, SMEM_SZ>>>(p, t);
    }
}

// round 11
// speedup vs baseline: 1.0807x; 1.0807x over previous
#include <cuda_runtime.h>
#include <cuda_bf16.h>
#include <cstdint>
#include <math.h>

#define BATCH 8192
#define TSTEPS 16
#define NTHR 512

#if defined(__CUDA_ARCH__) && (defined(__CUDA_ARCH_FEAT_SM103_ALL) || defined(__CUDA_ARCH_FEAT_SM100_ALL) || \
    (defined(__CUDA_ARCH_SPECIFIC__) && (__CUDA_ARCH_SPECIFIC__ >= 1000)) || \
    (defined(__CUDA_ARCH_FAMILY_SPECIFIC__) && (__CUDA_ARCH_FAMILY_SPECIFIC__ >= 1000)))
#define USE_TC 1
#else
#define USE_TC 0
#endif

#define SM_AH0 1024
#define SM_AL0 17408
#define SM_BH0 33792
#define SM_BL0 66560
#define SM_AH1 99328
#define SM_AL1 115712
#define SM_BH1 132096
#define SM_BL1 164864
#define SMEM_SZ 197632
#define SW128(x) ((x) ^ (((x) >> 3) & 0x70))

#define WTOT 344064
#define WS3  229376
__device__ __nv_bfloat16 g_wh[WTOT];
__device__ __nv_bfloat16 g_wl[WTOT];
__device__ float g_cue[BATCH * 2];
__device__ float g_w3c0[256], g_w3c1[256];

static __device__ __forceinline__ uint32_t smem_u32(const void* p) {
    uint32_t a;
    asm("{ .reg .u64 t; cvta.to.shared.u64 t, %1; cvt.u32.u64 %0, t; }" : "=r"(a) : "l"(p));
    return a;
}
static __device__ __forceinline__ float ftanh(float x) {
    float r;
    asm("tanh.approx.f32 %0, %1;" : "=f"(r) : "f"(x));
    return r;
}
#if USE_TC
static __device__ __forceinline__ uint32_t elect_one() {
    uint32_t p;
    asm volatile("{ .reg .pred p; elect.sync _|p, 0xFFFFFFFF; selp.b32 %0, 1, 0, p; }" : "=r"(p));
    return p;
}
#endif
#define MBARRIER_INIT(a, c) \
    asm volatile("mbarrier.init.shared.b64 [%0], %1;" :: "r"((uint32_t)(a)), "r"((uint32_t)(c)) : "memory")
#define MBAR_WAIT(mb, par) do { \
    uint32_t _m = (uint32_t)(mb), _p = (uint32_t)(par), _d = 0; \
    for (int _i = 0; _i < (1 << 20) && !_d; _i++) { \
        asm volatile("{ .reg .pred p; mbarrier.test_wait.parity.acquire.cta.shared::cta.b64 p, [%1], %2; selp.b32 %0,1,0,p; }" \
            : "=r"(_d) : "r"(_m), "r"(_p) : "memory"); \
    } \
} while (0)
#define TC_ALLOC(a, n) asm volatile("tcgen05.alloc.cta_group::1.sync.aligned.shared::cta.b32 [%0], %1;" :: "r"((uint32_t)(a)), "r"((uint32_t)(n)) : "memory")
#define TC_DEALLOC(t, n) asm volatile("tcgen05.dealloc.cta_group::1.sync.aligned.b32 %0, %1;" :: "r"(t), "r"((uint32_t)(n)))
#define TC_RELINQ() asm volatile("tcgen05.relinquish_alloc_permit.cta_group::1.sync.aligned;")
#define TC_COMMIT(mb) asm volatile("tcgen05.commit.cta_group::1.mbarrier::arrive::one.shared::cluster.b64 [%0];" :: "r"((uint32_t)(mb)) : "memory")
#define TC_FENCE_BEFORE() asm volatile("tcgen05.fence::before_thread_sync;" ::: "memory")
#define TC_FENCE_AFTER()  asm volatile("tcgen05.fence::after_thread_sync;"  ::: "memory")
#define TC_WAIT_LD() asm volatile("tcgen05.wait::ld.sync.aligned;" ::: "memory")
#define FENCE_ASYNC() asm volatile("fence.proxy.async.shared::cta;" ::: "memory")

#define TC_LD_X32(r, a) \
    asm volatile("tcgen05.ld.sync.aligned.32x32b.x32.b32 " \
        "{%0,%1,%2,%3,%4,%5,%6,%7,%8,%9,%10,%11,%12,%13,%14,%15," \
        "%16,%17,%18,%19,%20,%21,%22,%23,%24,%25,%26,%27,%28,%29,%30,%31}, [%32];" \
        : "=r"((r)[0]),"=r"((r)[1]),"=r"((r)[2]),"=r"((r)[3]),"=r"((r)[4]),"=r"((r)[5]),"=r"((r)[6]),"=r"((r)[7]), \
          "=r"((r)[8]),"=r"((r)[9]),"=r"((r)[10]),"=r"((r)[11]),"=r"((r)[12]),"=r"((r)[13]),"=r"((r)[14]),"=r"((r)[15]), \
          "=r"((r)[16]),"=r"((r)[17]),"=r"((r)[18]),"=r"((r)[19]),"=r"((r)[20]),"=r"((r)[21]),"=r"((r)[22]),"=r"((r)[23]), \
          "=r"((r)[24]),"=r"((r)[25]),"=r"((r)[26]),"=r"((r)[27]),"=r"((r)[28]),"=r"((r)[29]),"=r"((r)[30]),"=r"((r)[31]) \
        : "r"(a))

#define DESC_BASE ((2ull << 61) | (1ull << 46) | (64ull << 32) | (1ull << 16))
#define MKDESC(a) (DESC_BASE | (uint64_t)((((uint32_t)(a)) >> 4) & 0x3FFF))
#define ID_N256 ((1u << 4) | (1u << 7) | (1u << 10) | (32u << 17) | (8u << 24))
#define ID_N64  ((1u << 4) | (1u << 7) | (1u << 10) | (8u << 17)  | (8u << 24))

#if USE_TC
static __device__ __forceinline__ void mma_f16(uint32_t d, uint64_t a, uint64_t b,
                                               uint32_t idesc, uint32_t en) {
    asm volatile("{ .reg .pred p; setp.ne.u32 p, %5, 0; "
                 "tcgen05.mma.cta_group::1.kind::f16 [%0], %1, %2, %3, {%4,%4,%4,%4}, p; }"
                 :: "r"(d), "l"(a), "l"(b), "r"(idesc), "r"(0u), "r"(en) : "memory");
}
#endif

static __device__ __forceinline__ unsigned pk(float a, float b) {
    __nv_bfloat162 h = __floats2bfloat162_rn(a, b);
    return *reinterpret_cast<unsigned*>(&h);
}
static __device__ __forceinline__ float bfl(float x) {
    return __bfloat162float(__float2bfloat16_rn(x));
}

__global__ void prep_w(const float* __restrict__ W, int ld, int col0, int N, int nch,
                       int dstoff) {
    int idx = blockIdx.x * 256 + threadIdx.x;
    if (idx >= N * nch * 64) return;
    int chunk = idx / (N * 64), rem = idx - chunk * N * 64;
    int n = rem >> 6, k = rem & 63;
    float v = W[(size_t)n * ld + col0 + chunk * 64 + k];
    float h = bfl(v);
    int off = dstoff + chunk * N * 64 + (SW128(n * 128 + k * 2) >> 1);
    g_wh[off] = __float2bfloat16_rn(v);
    g_wl[off] = __float2bfloat16_rn(v - h);
}
__global__ void prep_cue_w(const float* __restrict__ W3i) {
    int i = threadIdx.x;
    g_w3c0[i] = W3i[(size_t)i * 130];
    g_w3c1[i] = W3i[(size_t)i * 130 + 1];
}

// A staging: 128 rows x 16 float4 = 2048 units over NTHR threads.
static __device__ __forceinline__ void stgA(char* hiD, char* loD, const float* __restrict__ S,
                                            int ld, int c0, int tid) {
#pragma unroll
    for (int q = 0; q < 2048 / NTHR; q++) {
        int lin = tid + q * NTHR, row = lin >> 4, g = lin & 15;
        float4 v = *reinterpret_cast<const float4*>(S + (size_t)row * ld + c0 + g * 4);
        float hx = bfl(v.x), hy = bfl(v.y), hz = bfl(v.z), hw = bfl(v.w);
        uint2 H, L;
        H.x = pk(v.x, v.y); H.y = pk(v.z, v.w);
        L.x = pk(v.x - hx, v.y - hy); L.y = pk(v.z - hz, v.w - hw);
        int off = SW128(row * 128 + g * 8);
        *reinterpret_cast<uint2*>(hiD + off) = H;
        *reinterpret_cast<uint2*>(loD + off) = L;
    }
}

#if USE_TC
struct Ctx {
    uint32_t sb, tb;
    int tid, ph;
    int use_[2];
    __device__ __forceinline__ uint32_t mb(int b) const { return sb + 8 + 8 * b; }
    __device__ __forceinline__ void wait_buf(int b) {
        if (use_[b] > 0) MBAR_WAIT(mb(b), (uint32_t)((use_[b] - 1) & 1));
    }
    __device__ __forceinline__ void wait_all() {
        int lb = (ph - 1) & 1;
        MBAR_WAIT(mb(lb), (uint32_t)((use_[lb] - 1) & 1));
    }
};
template <int NB>
static __device__ __forceinline__ void gemm_seg(Ctx& c, char* sm,
                                                const float* A, int ldA, int woff,
                                                int nch, uint32_t dtm, uint32_t idesc,
                                                bool fresh) {
    for (int kc = 0; kc < nch; kc++) {
        int b = c.ph & 1;
        c.wait_buf(b);
        char* AH = sm + (b ? SM_AH1 : SM_AH0);
        char* AL = sm + (b ? SM_AL1 : SM_AL0);
        stgA(AH, AL, A, ldA, kc * 64, c.tid);
        {
            const uint4* sh = reinterpret_cast<const uint4*>(g_wh + woff + (size_t)kc * NB * 64);
            const uint4* sl = reinterpret_cast<const uint4*>(g_wl + woff + (size_t)kc * NB * 64);
            uint4* dh = reinterpret_cast<uint4*>(sm + (b ? SM_BH1 : SM_BH0));
            uint4* dl = reinterpret_cast<uint4*>(sm + (b ? SM_BL1 : SM_BL0));
#pragma unroll
            for (int q = 0; q < NB * 8 / NTHR; q++) {
                int i = c.tid + q * NTHR;
                dh[i] = sh[i];
                dl[i] = sl[i];
            }
        }
        FENCE_ASYNC();
        __syncthreads();
        if ((c.tid >> 5) == 0 && elect_one()) {
            TC_FENCE_AFTER();
            uint64_t ah = MKDESC(c.sb + (b ? SM_AH1 : SM_AH0));
            uint64_t al = MKDESC(c.sb + (b ? SM_AL1 : SM_AL0));
            uint64_t bh = MKDESC(c.sb + (b ? SM_BH1 : SM_BH0));
            uint64_t bl = MKDESC(c.sb + (b ? SM_BL1 : SM_BL0));
#pragma unroll
            for (int s = 0; s < 4; s++)
                mma_f16(dtm, ah + 2 * s, bh + 2 * s, idesc, (fresh && kc == 0 && s == 0) ? 0u : 1u);
#pragma unroll
            for (int s = 0; s < 4; s++) mma_f16(dtm, ah + 2 * s, bl + 2 * s, idesc, 1u);
#pragma unroll
            for (int s = 0; s < 4; s++) mma_f16(dtm, al + 2 * s, bh + 2 * s, idesc, 1u);
            TC_COMMIT(c.mb(b));
        }
        c.use_[b]++;
        c.ph++;
    }
}
#endif

// ---- FFMA fallback (blockDim-robust: strided loads, compute guarded tid<256) ----
static __device__ void fg256(float acc[8][8], const float* __restrict__ A, int ldA, int K,
                             const float* __restrict__ W, int ldW, int col0, int mode,
                             float* Ws, float* As, int tid, int tr, int tc) {
    for (int k0 = 0; k0 < K; k0 += 32) {
        __syncthreads();
        if (mode == 0) {
            for (int lin = tid; lin < 2048; lin += NTHR) {
                int n = lin >> 3, p4 = lin & 7;
                float4 v = *reinterpret_cast<const float4*>(W + (size_t)n * ldW + col0 + k0 + p4 * 4);
                Ws[(p4 * 4 + 0) * 260 + n] = v.x; Ws[(p4 * 4 + 1) * 260 + n] = v.y;
                Ws[(p4 * 4 + 2) * 260 + n] = v.z; Ws[(p4 * 4 + 3) * 260 + n] = v.w;
            }
        } else {
            for (int lin = tid; lin < 4096; lin += NTHR) {
                int n = lin >> 4, g = lin & 15;
                float2 v = *reinterpret_cast<const float2*>(W + (size_t)n * ldW + col0 + k0 + g * 2);
                Ws[(g * 2 + 0) * 260 + n] = v.x;
                Ws[(g * 2 + 1) * 260 + n] = v.y;
            }
        }
        for (int lin = tid; lin < 512; lin += NTHR) {
            int row = lin >> 3, p4 = lin & 7;
            float4 v = *reinterpret_cast<const float4*>(A + (size_t)row * ldA + k0 + p4 * 4);
            As[(p4 * 4 + 0) * 65 + row] = v.x; As[(p4 * 4 + 1) * 65 + row] = v.y;
            As[(p4 * 4 + 2) * 65 + row] = v.z; As[(p4 * 4 + 3) * 65 + row] = v.w;
        }
        __syncthreads();
        if (tid < 256) {
#pragma unroll 4
            for (int kk = 0; kk < 32; kk++) {
                float a[8], w[8];
#pragma unroll
                for (int i = 0; i < 8; i++) a[i] = As[kk * 65 + tr + 8 * i];
#pragma unroll
                for (int j = 0; j < 8; j++) w[j] = Ws[kk * 260 + tc + 32 * j];
#pragma unroll
                for (int i = 0; i < 8; i++)
#pragma unroll
                    for (int j = 0; j < 8; j++) acc[i][j] = fmaf(a[i], w[j], acc[i][j]);
            }
        }
    }
}
static __device__ void fg64(float acc[8][2], const float* __restrict__ A, int ldA, int K,
                            const float* __restrict__ W, float* Ws, float* As,
                            int tid, int tr, int tc) {
    for (int k0 = 0; k0 < K; k0 += 32) {
        __syncthreads();
        for (int lin = tid; lin < 512; lin += NTHR) {
            int n = lin >> 3, p4 = lin & 7;
            float4 v = *reinterpret_cast<const float4*>(W + (size_t)n * 256 + k0 + p4 * 4);
            Ws[(p4 * 4 + 0) * 65 + n] = v.x; Ws[(p4 * 4 + 1) * 65 + n] = v.y;
            Ws[(p4 * 4 + 2) * 65 + n] = v.z; Ws[(p4 * 4 + 3) * 65 + n] = v.w;
        }
        for (int lin = tid; lin < 512; lin += NTHR) {
            int row = lin >> 3, p4 = lin & 7;
            float4 v = *reinterpret_cast<const float4*>(A + (size_t)row * ldA + k0 + p4 * 4);
            As[(p4 * 4 + 0) * 65 + row] = v.x; As[(p4 * 4 + 1) * 65 + row] = v.y;
            As[(p4 * 4 + 2) * 65 + row] = v.z; As[(p4 * 4 + 3) * 65 + row] = v.w;
        }
        __syncthreads();
        if (tid < 256) {
#pragma unroll 8
            for (int kk = 0; kk < 32; kk++) {
                float a[8];
#pragma unroll
                for (int i = 0; i < 8; i++) a[i] = As[kk * 65 + tr + 8 * i];
                float w0 = Ws[kk * 65 + tc], w1 = Ws[kk * 65 + tc + 32];
#pragma unroll
                for (int i = 0; i < 8; i++) {
                    acc[i][0] = fmaf(a[i], w0, acc[i][0]);
                    acc[i][1] = fmaf(a[i], w1, acc[i][1]);
                }
            }
        }
    }
}

struct Params {
    const float* x;
    const float *W1i, *b1i, *W1h, *b1h, *Wf1, *bf1, *W1o, *b1o;
    const float *W2i, *b2i, *W2h, *b2h, *Wf2, *bf2, *W2o, *b2o;
    const float *W3i, *b3i, *W3h, *b3h, *W3o, *b3o, *Wfc, *bfc;
    float *h1, *h2, *h3, *h4;
    float *oseq, *o1, *o2, *f1, *f2, *ofa;
};

__global__ void init_kernel(const float* __restrict__ cue,
                            const float* __restrict__ hc1, const float* __restrict__ hc2,
                            const float* __restrict__ hc3, const float* __restrict__ hc4,
                            float* __restrict__ h1, float* __restrict__ h2,
                            float* __restrict__ h3, float* __restrict__ h4,
                            float* __restrict__ cue_arr) {
    int idx = blockIdx.x * blockDim.x + threadIdx.x;
    if (idx < BATCH * 256) { h1[idx] = hc1[idx]; h2[idx] = hc2[idx]; h3[idx] = hc3[idx]; }
    if (idx < BATCH * 64) h4[idx] = hc4[idx];
    if (idx < BATCH) {
        float c = cue[idx], c0 = c * 10.0f, c1 = 10.0f * fabsf(c - 1.0f);
        g_cue[idx * 2] = c0; g_cue[idx * 2 + 1] = c1;
#pragma unroll
        for (int t = 0; t < TSTEPS; t++) {
            cue_arr[(size_t)t * BATCH * 2 + idx * 2] = c0;
            cue_arr[(size_t)t * BATCH * 2 + idx * 2 + 1] = c1;
        }
    }
}

__global__ __launch_bounds__(NTHR, 1) __cluster_dims__(1, 1, 1) void stack12_k(Params p, int t) {
    extern __shared__ char sm[];
    const int tid = threadIdx.x, wid = tid >> 5, lane = tid & 31;
    const int s = blockIdx.y, row0 = blockIdx.x * 128;

    const float* bi = s ? p.b2i : p.b1i;
    const float* bh = s ? p.b2h : p.b1h;
    const float* bf = s ? p.bf2 : p.bf1;
    const float* bo = s ? p.b2o : p.b1o;
    float* hst  = (s ? p.h2 : p.h1) + (size_t)row0 * 256;
    float* fout = (s ? p.f2 : p.f1) + ((size_t)t * BATCH + row0) * 256;
    float* oout = (s ? p.o2 : p.o1) + ((size_t)t * BATCH + row0) * 64;
    const float* xt = p.x + ((size_t)t * BATCH + row0) * 64;
    const float* h4 = p.h4 + (size_t)row0 * 64;

#if USE_TC
    const int woff = s ? 114688 : 0;
    const uint32_t sb = smem_u32(sm);
    if (wid == 0) { TC_ALLOC(sb, 512); TC_RELINQ(); }
    if (tid == 0) { MBARRIER_INIT(sb + 8, 1); MBARRIER_INIT(sb + 16, 1); }
    __syncthreads();
    uint32_t tb;
    asm volatile("ld.shared.b32 %0, [%1];" : "=r"(tb) : "r"(sb));
    Ctx c{sb, tb, tid, 0, {0, 0}};

    const int sub = wid & 3, r = sub * 32 + lane, cg = wid >> 2;   // 16 warps: 4 subs x 4 col groups

    // Fused chain: D2 = feed; D1 = x@Wi + h@Wh
    gemm_seg<256>(c, sm, h4, 64, woff + 0, 1, tb + 256, ID_N256, true);
    gemm_seg<256>(c, sm, xt, 64, woff + 16384, 1, tb, ID_N256, true);
    gemm_seg<256>(c, sm, hst, 256, woff + 32768, 4, tb, ID_N256, false);
    c.wait_all();
    TC_FENCE_AFTER();
#pragma unroll
    for (int cc = 0; cc < 2; cc++) {
        int gc = cg * 64 + cc * 32;
        uint32_t rg2[32];
        TC_LD_X32(rg2, tb + 256 + gc);
        TC_WAIT_LD();
        float seed[32];
#pragma unroll
        for (int j = 0; j < 32; j++) {
            float fv = __uint_as_float(rg2[j]) + bf[gc + j];
            rg2[j] = __float_as_uint(fv);
            seed[j] = ftanh(fv) + bi[gc + j] + bh[gc + j];
        }
#pragma unroll
        for (int j4 = 0; j4 < 8; j4++)
            *reinterpret_cast<float4*>(fout + (size_t)r * 256 + gc + j4 * 4) =
                make_float4(__uint_as_float(rg2[j4 * 4]), __uint_as_float(rg2[j4 * 4 + 1]),
                            __uint_as_float(rg2[j4 * 4 + 2]), __uint_as_float(rg2[j4 * 4 + 3]));
        uint32_t rg1[32];
        TC_LD_X32(rg1, tb + gc);
        TC_WAIT_LD();
#pragma unroll
        for (int j4 = 0; j4 < 8; j4++)
            *reinterpret_cast<float4*>(hst + (size_t)r * 256 + gc + j4 * 4) =
                make_float4(ftanh(__uint_as_float(rg1[j4 * 4]) + seed[j4 * 4]),
                            ftanh(__uint_as_float(rg1[j4 * 4 + 1]) + seed[j4 * 4 + 1]),
                            ftanh(__uint_as_float(rg1[j4 * 4 + 2]) + seed[j4 * 4 + 2]),
                            ftanh(__uint_as_float(rg1[j4 * 4 + 3]) + seed[j4 * 4 + 3]));
    }
    TC_FENCE_BEFORE();
    __syncthreads();

    gemm_seg<64>(c, sm, hst, 256, woff + 98304, 4, tb + 256, ID_N64, true);
    c.wait_all();
    TC_FENCE_AFTER();
    if (cg < 2) {
        int cb = cg * 32;
        uint32_t rg[32];
        TC_LD_X32(rg, tb + 256 + cb);
        TC_WAIT_LD();
#pragma unroll
        for (int j4 = 0; j4 < 8; j4++)
            *reinterpret_cast<float4*>(oout + (size_t)r * 64 + cb + j4 * 4) =
                make_float4(ftanh(__uint_as_float(rg[j4 * 4]) + bo[cb + j4 * 4]),
                            ftanh(__uint_as_float(rg[j4 * 4 + 1]) + bo[cb + j4 * 4 + 1]),
                            ftanh(__uint_as_float(rg[j4 * 4 + 2]) + bo[cb + j4 * 4 + 2]),
                            ftanh(__uint_as_float(rg[j4 * 4 + 3]) + bo[cb + j4 * 4 + 3]));
    }
    TC_FENCE_BEFORE();
    __syncthreads();
    if (wid == 0) TC_DEALLOC(tb, 512);
#else
    const float* Wi = s ? p.W2i : p.W1i;
    const float* Wh = s ? p.W2h : p.W1h;
    const float* Wf = s ? p.Wf2 : p.Wf1;
    const float* Wo = s ? p.W2o : p.W1o;
    float* Ws = reinterpret_cast<float*>(sm);
    float* As = Ws + 32 * 260;
    const int tr = wid & 7, tc = lane;
    for (int hf = 0; hf < 2; hf++) {
        const float* Ah4 = h4 + hf * 64 * 64;
        const float* Axt = xt + hf * 64 * 64;
        float* hh = hst + hf * 64 * 256;
        float* ff = fout + hf * 64 * 256;
        float* oo = oout + hf * 64 * 64;

        float acc[8][8];
#pragma unroll
        for (int i = 0; i < 8; i++)
#pragma unroll
            for (int j = 0; j < 8; j++) acc[i][j] = 0.0f;
        fg256(acc, Ah4, 64, 64, Wf, 64, 0, 0, Ws, As, tid, tr, tc);
        if (tid < 256) {
#pragma unroll
            for (int i = 0; i < 8; i++) {
                int rr = tr + 8 * i;
#pragma unroll
                for (int j = 0; j < 8; j++) {
                    int cc = tc + 32 * j;
                    float fv = acc[i][j] + bf[cc];
                    ff[rr * 256 + cc] = fv;
                    acc[i][j] = tanhf(fv) + bi[cc] + bh[cc];
                }
            }
        }
        fg256(acc, Axt, 64, 64, Wi, 64, 0, 0, Ws, As, tid, tr, tc);
        fg256(acc, hh, 256, 256, Wh, 256, 0, 0, Ws, As, tid, tr, tc);
        if (tid < 256) {
#pragma unroll
            for (int i = 0; i < 8; i++) {
                int rr = tr + 8 * i;
#pragma unroll
                for (int j = 0; j < 8; j++) hh[rr * 256 + tc + 32 * j] = tanhf(acc[i][j]);
            }
        }
        __syncthreads();
        float oacc[8][2];
#pragma unroll
        for (int i = 0; i < 8; i++) { oacc[i][0] = 0.0f; oacc[i][1] = 0.0f; }
        fg64(oacc, hh, 256, 256, Wo, Ws, As, tid, tr, tc);
        if (tid < 256) {
#pragma unroll
            for (int i = 0; i < 8; i++) {
                int rr = tr + 8 * i;
                oo[rr * 64 + tc]      = tanhf(oacc[i][0] + bo[tc]);
                oo[rr * 64 + tc + 32] = tanhf(oacc[i][1] + bo[tc + 32]);
            }
        }
        __syncthreads();
    }
#endif
}

__global__ __launch_bounds__(NTHR, 1) __cluster_dims__(1, 1, 1) void stack3_k(Params p, int t) {
    extern __shared__ char sm[];
    const int tid = threadIdx.x, wid = tid >> 5, lane = tid & 31;
    const int row0 = blockIdx.x * 128;

    const float* o1t = p.o1 + ((size_t)t * BATCH + row0) * 64;
    const float* o2t = p.o2 + ((size_t)t * BATCH + row0) * 64;
    float* h3 = p.h3 + (size_t)row0 * 256;
    float* h4 = p.h4 + (size_t)row0 * 64;

#if USE_TC
    const uint32_t sb = smem_u32(sm);
    if (wid == 0) { TC_ALLOC(sb, 512); TC_RELINQ(); }
    if (tid == 0) { MBARRIER_INIT(sb + 8, 1); MBARRIER_INIT(sb + 16, 1); }
    __syncthreads();
    uint32_t tb;
    asm volatile("ld.shared.b32 %0, [%1];" : "=r"(tb) : "r"(sb));
    Ctx c{sb, tb, tid, 0, {0, 0}};

    const int sub = wid & 3, r = sub * 32 + lane, cg = wid >> 2;

    gemm_seg<256>(c, sm, o1t, 64, WS3 + 0, 1, tb, ID_N256, true);
    gemm_seg<256>(c, sm, o2t, 64, WS3 + 16384, 1, tb, ID_N256, false);
    gemm_seg<256>(c, sm, h3, 256, WS3 + 32768, 4, tb, ID_N256, false);
    c.wait_all();
    TC_FENCE_AFTER();
    {
        float c0 = g_cue[(row0 + r) * 2], c1 = g_cue[(row0 + r) * 2 + 1];
#pragma unroll
        for (int cc = 0; cc < 2; cc++) {
            int gc = cg * 64 + cc * 32;
            uint32_t rg[32];
            TC_LD_X32(rg, tb + gc);
            TC_WAIT_LD();
            float hv[32];
#pragma unroll
            for (int j = 0; j < 32; j++) {
                int col = gc + j;
                hv[j] = ftanh(__uint_as_float(rg[j]) + c0 * g_w3c0[col] + c1 * g_w3c1[col] +
                              p.b3i[col] + p.b3h[col]);
            }
#pragma unroll
            for (int j4 = 0; j4 < 8; j4++)
                *reinterpret_cast<float4*>(h3 + (size_t)r * 256 + gc + j4 * 4) =
                    make_float4(hv[j4 * 4], hv[j4 * 4 + 1], hv[j4 * 4 + 2], hv[j4 * 4 + 3]);
        }
    }
    TC_FENCE_BEFORE();
    __syncthreads();

    gemm_seg<64>(c, sm, h3, 256, WS3 + 98304, 4, tb + 256, ID_N64, true);
    c.wait_all();
    TC_FENCE_AFTER();
    float* ofs = reinterpret_cast<float*>(sm + 1024);
    if (cg < 2) {
        int cb = cg * 32;
        uint32_t rg[32];
        TC_LD_X32(rg, tb + 256 + cb);
        TC_WAIT_LD();
        float ov[32];
#pragma unroll
        for (int j = 0; j < 32; j++) {
            float o = __uint_as_float(rg[j]) + p.b3o[cb + j];
            ov[j] = o;
            ofs[r * 65 + cb + j] = fmaxf(o, 0.0f);
        }
#pragma unroll
        for (int j4 = 0; j4 < 8; j4++) {
            *reinterpret_cast<float4*>(h4 + (size_t)r * 64 + cb + j4 * 4) =
                make_float4(ov[j4 * 4], ov[j4 * 4 + 1], ov[j4 * 4 + 2], ov[j4 * 4 + 3]);
            *reinterpret_cast<float4*>(p.ofa + ((size_t)t * BATCH + row0 + r) * 64 + cb + j4 * 4) =
                make_float4(fmaxf(ov[j4 * 4], 0.0f), fmaxf(ov[j4 * 4 + 1], 0.0f),
                            fmaxf(ov[j4 * 4 + 2], 0.0f), fmaxf(ov[j4 * 4 + 3], 0.0f));
        }
    }
    TC_FENCE_BEFORE();
    __syncthreads();
    if (tid < 256) {
        int rr = tid >> 1, cc2 = tid & 1;
        float sum = p.bfc[cc2];
#pragma unroll
        for (int k = 0; k < 64; k++) sum = fmaf(ofs[rr * 65 + k], p.Wfc[cc2 * 64 + k], sum);
        p.oseq[((size_t)t * BATCH + row0 + rr) * 2 + cc2] = sum;
    }
    __syncthreads();
    if (wid == 0) TC_DEALLOC(tb, 512);
#else
    float* Ws = reinterpret_cast<float*>(sm);
    float* As = Ws + 32 * 260;
    float* ofs = reinterpret_cast<float*>(sm + 48 * 1024);
    const int tr = wid & 7, tc = lane;
    for (int hf = 0; hf < 2; hf++) {
        const int r0g = row0 + hf * 64;
        const float* Ao1 = o1t + hf * 64 * 64;
        const float* Ao2 = o2t + hf * 64 * 64;
        float* hh = h3 + hf * 64 * 256;
        float* h4h = h4 + hf * 64 * 64;

        float acc[8][8];
#pragma unroll
        for (int i = 0; i < 8; i++) {
            int rg = r0g + tr + 8 * i;
            float c0 = g_cue[rg * 2], c1 = g_cue[rg * 2 + 1];
#pragma unroll
            for (int j = 0; j < 8; j++) {
                int col = tc + 32 * j;
                acc[i][j] = c0 * p.W3i[(size_t)col * 130] + c1 * p.W3i[(size_t)col * 130 + 1];
            }
        }
        fg256(acc, Ao1, 64, 64, p.W3i, 130, 2, 1, Ws, As, tid, tr, tc);
        fg256(acc, Ao2, 64, 64, p.W3i, 130, 66, 1, Ws, As, tid, tr, tc);
        fg256(acc, hh, 256, 256, p.W3h, 256, 0, 0, Ws, As, tid, tr, tc);
        if (tid < 256) {
#pragma unroll
            for (int i = 0; i < 8; i++) {
                int rr = tr + 8 * i;
#pragma unroll
                for (int j = 0; j < 8; j++) {
                    int col = tc + 32 * j;
                    hh[rr * 256 + col] = tanhf(acc[i][j] + p.b3i[col] + p.b3h[col]);
                }
            }
        }
        __syncthreads();
        float oacc[8][2];
#pragma unroll
        for (int i = 0; i < 8; i++) { oacc[i][0] = 0.0f; oacc[i][1] = 0.0f; }
        fg64(oacc, hh, 256, 256, p.W3o, Ws, As, tid, tr, tc);
        if (tid < 256) {
#pragma unroll
            for (int i = 0; i < 8; i++) {
                int rr = tr + 8 * i;
#pragma unroll
                for (int j = 0; j < 2; j++) {
                    int col = tc + 32 * j;
                    float o = oacc[i][j] + p.b3o[col];
                    float of = fmaxf(o, 0.0f);
                    h4h[rr * 64 + col] = o;
                    p.ofa[((size_t)t * BATCH + r0g + rr) * 64 + col] = of;
                    ofs[rr * 66 + col] = of;
                }
            }
        }
        __syncthreads();
        if (tid < 128) {
            int rr = tid >> 1, cc2 = tid & 1;
            float sum = p.bfc[cc2];
#pragma unroll
            for (int k = 0; k < 64; k++) sum = fmaf(ofs[rr * 66 + k], p.Wfc[cc2 * 64 + k], sum);
            p.oseq[((size_t)t * BATCH + r0g + rr) * 2 + cc2] = sum;
        }
        __syncthreads();
    }
#endif
}

extern "C" void kernel_launch(void* const* d_in, const int* in_sizes, int n_in,
                              void* d_out, int out_size) {
    float* out = (float*)d_out;
    size_t off = 0;
    float* oseq = out + off; off += (size_t)TSTEPS * BATCH * 2;
    float* h1 = out + off; off += (size_t)BATCH * 256;
    float* h2 = out + off; off += (size_t)BATCH * 256;
    float* h3 = out + off; off += (size_t)BATCH * 256;
    float* h4 = out + off; off += (size_t)BATCH * 64;
    float* o1 = out + off; off += (size_t)TSTEPS * BATCH * 64;
    float* o2 = out + off; off += (size_t)TSTEPS * BATCH * 64;
    float* cue_arr = out + off; off += (size_t)TSTEPS * BATCH * 2;
    float* f1 = out + off; off += (size_t)TSTEPS * BATCH * 256;
    float* f2 = out + off; off += (size_t)TSTEPS * BATCH * 256;
    float* ofa = out + off;

    Params p;
    p.x = (const float*)d_in[0];
    p.W1i = (const float*)d_in[6];  p.b1i = (const float*)d_in[7];
    p.W1h = (const float*)d_in[8];  p.b1h = (const float*)d_in[9];
    p.Wf1 = (const float*)d_in[10]; p.bf1 = (const float*)d_in[11];
    p.W1o = (const float*)d_in[12]; p.b1o = (const float*)d_in[13];
    p.W2i = (const float*)d_in[14]; p.b2i = (const float*)d_in[15];
    p.W2h = (const float*)d_in[16]; p.b2h = (const float*)d_in[17];
    p.Wf2 = (const float*)d_in[18]; p.bf2 = (const float*)d_in[19];
    p.W2o = (const float*)d_in[20]; p.b2o = (const float*)d_in[21];
    p.W3i = (const float*)d_in[22]; p.b3i = (const float*)d_in[23];
    p.W3h = (const float*)d_in[24]; p.b3h = (const float*)d_in[25];
    p.W3o = (const float*)d_in[26]; p.b3o = (const float*)d_in[27];
    p.Wfc = (const float*)d_in[28]; p.bfc = (const float*)d_in[29];
    p.h1 = h1; p.h2 = h2; p.h3 = h3; p.h4 = h4;
    p.oseq = oseq; p.o1 = o1; p.o2 = o2; p.f1 = f1; p.f2 = f2; p.ofa = ofa;

    cudaFuncSetAttribute(stack12_k, cudaFuncAttributeMaxDynamicSharedMemorySize, SMEM_SZ);
    cudaFuncSetAttribute(stack3_k, cudaFuncAttributeMaxDynamicSharedMemorySize, SMEM_SZ);

    struct { const float* W; int ld, col0, N, nch, dst; } pw[12] = {
        {p.Wf1, 64, 0, 256, 1, 0},        {p.W1i, 64, 0, 256, 1, 16384},
        {p.W1h, 256, 0, 256, 4, 32768},   {p.W1o, 256, 0, 64, 4, 98304},
        {p.Wf2, 64, 0, 256, 1, 114688},   {p.W2i, 64, 0, 256, 1, 131072},
        {p.W2h, 256, 0, 256, 4, 147456},  {p.W2o, 256, 0, 64, 4, 212992},
        {p.W3i, 130, 2, 256, 1, WS3},     {p.W3i, 130, 66, 256, 1, WS3 + 16384},
        {p.W3h, 256, 0, 256, 4, WS3 + 32768}, {p.W3o, 256, 0, 64, 4, WS3 + 98304},
    };
    for (int i = 0; i < 12; i++) {
        int n = pw[i].N * pw[i].nch * 64;
        prep_w<<<(n + 255) / 256, 256>>>(pw[i].W, pw[i].ld, pw[i].col0,
                                         pw[i].N, pw[i].nch, pw[i].dst);
    }
    prep_cue_w<<<1, 256>>>(p.W3i);

    init_kernel<<<(BATCH * 256) / 256, 256>>>((const float*)d_in[1], (const float*)d_in[2],
                                              (const float*)d_in[3], (const float*)d_in[4],
                                              (const float*)d_in[5], h1, h2, h3, h4, cue_arr);
    for (int t = 0; t < TSTEPS; t++) {
        stack12_k<<<dim3(BATCH / 128, 2), NTHR, SMEM_SZ>>>(p, t);
        stack3_k<<<BATCH / 128, NTHR, SMEM_SZ>>>(p, t);
    }
}